// round 8
// baseline (speedup 1.0000x reference)
#include <cuda_runtime.h>
#include <cstdint>
#include <cstddef>

// ---------------------------------------------------------------------------
// Problem constants (fixed shapes per reference)
// ---------------------------------------------------------------------------
#define NU    100000
#define NI    50000
#define KDIM  256
#define MSGD  128
#define OUTD  128
#define RREL  5
#define NE    1000000
#define NCOMB (RREL * OUTD)   // 640

// ---------------------------------------------------------------------------
// Static device scratch (no runtime allocation allowed)
// ---------------------------------------------------------------------------
static __device__ float g_xu[(size_t)NU * NCOMB];     // 256 MB: per-relation user messages (post W-combine)
static __device__ float g_xi[(size_t)NI * NCOMB];     // 128 MB: per-relation item messages
static __device__ float g_accu[(size_t)NU * OUTD];    // 51.2 MB
static __device__ float g_acci[(size_t)NI * OUTD];    // 25.6 MB
static __device__ float g_wcu[KDIM * NCOMB];          // W_u[r] @ Wi_fc_r   (user feats -> item outputs)
static __device__ float g_wci[KDIM * NCOMB];          // W_i[r] @ Wu_fc_r   (item feats -> user outputs)

// ---------------------------------------------------------------------------
// Kernel 1: combine weights  Wc[k][r*128+o] = sum_m W[r,k,m] * Wfc[r*128+m, o]
// ---------------------------------------------------------------------------
__global__ void combine_w_kernel(const float* __restrict__ W,
                                 const float* __restrict__ Wfc,
                                 float* __restrict__ Wc)
{
    int idx = blockIdx.x * blockDim.x + threadIdx.x;
    if (idx >= KDIM * NCOMB) return;
    int k = idx / NCOMB;
    int c = idx - k * NCOMB;
    int r = c / OUTD;
    int o = c - r * OUTD;
    const float* wrow = W + ((size_t)r * KDIM + k) * MSGD;
    const float* fc   = Wfc + ((size_t)r * MSGD) * OUTD + o;
    float s = 0.f;
#pragma unroll 8
    for (int m = 0; m < MSGD; ++m)
        s += wrow[m] * fc[(size_t)m * OUTD];
    Wc[idx] = s;
}

// ---------------------------------------------------------------------------
// Kernel 2: zero accumulators
// ---------------------------------------------------------------------------
__global__ void zero_kernel(float4* __restrict__ p, int n4)
{
    int i = blockIdx.x * blockDim.x + threadIdx.x;
    if (i < n4) p[i] = make_float4(0.f, 0.f, 0.f, 0.f);
}

// ---------------------------------------------------------------------------
// Kernel 3: SGEMM  X[m, :] = (A[m, :256] @ B[256, 640]) * cj[m]
// 128x128 block tile, BK=8, 8x8 per-thread register tile, 256 threads.
// ---------------------------------------------------------------------------
__global__ __launch_bounds__(256, 1) void gemm_scale_kernel(
    const float* __restrict__ A,   // [M, 256]
    const float* __restrict__ B,   // [256, 640]
    const float* __restrict__ cj,  // [M]
    float* __restrict__ X,         // [M, 640]
    int M)
{
    constexpr int K = KDIM;
    constexpr int N = NCOMB;
    __shared__ float As[8][128];
    __shared__ float Bs[8][128];

    const int t = threadIdx.x;
    const int rowBase = blockIdx.y * 128;
    const int colBase = blockIdx.x * 128;

    const int aRow = t >> 1;            // 0..127
    const int aCol = (t & 1) << 2;      // 0 or 4
    const int bRow = t >> 5;            // 0..7
    const int bCol = (t & 31) << 2;     // 0..124

    const int tx = (t & 15) << 3;       // col offset in tile
    const int ty = (t >> 4) << 3;       // row offset in tile

    float acc[8][8];
#pragma unroll
    for (int i = 0; i < 8; ++i)
#pragma unroll
        for (int j = 0; j < 8; ++j) acc[i][j] = 0.f;

    const int grA = rowBase + aRow;
    const bool aValid = (grA < M);

    for (int k0 = 0; k0 < K; k0 += 8) {
        float4 av = make_float4(0.f, 0.f, 0.f, 0.f);
        if (aValid)
            av = *(const float4*)(A + (size_t)grA * K + k0 + aCol);
        As[aCol + 0][aRow] = av.x;
        As[aCol + 1][aRow] = av.y;
        As[aCol + 2][aRow] = av.z;
        As[aCol + 3][aRow] = av.w;

        float4 bv = *(const float4*)(B + (size_t)(k0 + bRow) * N + colBase + bCol);
        *(float4*)&Bs[bRow][bCol] = bv;

        __syncthreads();

#pragma unroll
        for (int k = 0; k < 8; ++k) {
            float a[8], b[8];
            *(float4*)&a[0] = *(const float4*)&As[k][ty];
            *(float4*)&a[4] = *(const float4*)&As[k][ty + 4];
            *(float4*)&b[0] = *(const float4*)&Bs[k][tx];
            *(float4*)&b[4] = *(const float4*)&Bs[k][tx + 4];
#pragma unroll
            for (int i = 0; i < 8; ++i)
#pragma unroll
                for (int j = 0; j < 8; ++j)
                    acc[i][j] += a[i] * b[j];
        }
        __syncthreads();
    }

#pragma unroll
    for (int i = 0; i < 8; ++i) {
        int gr = rowBase + ty + i;
        if (gr < M) {
            float c = cj[gr];
            float4 o0, o1;
            o0.x = acc[i][0] * c; o0.y = acc[i][1] * c;
            o0.z = acc[i][2] * c; o0.w = acc[i][3] * c;
            o1.x = acc[i][4] * c; o1.y = acc[i][5] * c;
            o1.z = acc[i][6] * c; o1.w = acc[i][7] * c;
            *(float4*)(X + (size_t)gr * N + colBase + tx)     = o0;
            *(float4*)(X + (size_t)gr * N + colBase + tx + 4) = o1;
        }
    }
}

// ---------------------------------------------------------------------------
// Kernel 4: edge scatter. One warp per edge: gather 128-float message row,
// vector-reduce-add into destination accumulator row.
// edge arrays are [R, E] flattened, so the flat warp index == r*NE + e.
// ---------------------------------------------------------------------------
__global__ __launch_bounds__(256) void scatter_kernel(
    const float* __restrict__ X,      // [n_src, 640]
    const int* __restrict__ esrc,     // [R*E]
    const int* __restrict__ edst,     // [R*E]
    float* __restrict__ acc)          // [n_dst, 128]
{
    long long w = (long long)blockIdx.x * 8 + (threadIdx.x >> 5);
    if (w >= (long long)RREL * NE) return;
    int lane = threadIdx.x & 31;
    int r = (int)(w / NE);
    int src = esrc[w];
    int dst = edst[w];

    const float4* xp = (const float4*)(X + (size_t)src * NCOMB + (size_t)r * OUTD);
    float4 v = xp[lane];

    float* ap = acc + (size_t)dst * OUTD + lane * 4;
    asm volatile("red.global.add.v4.f32 [%0], {%1, %2, %3, %4};"
                 :: "l"(ap), "f"(v.x), "f"(v.y), "f"(v.z), "f"(v.w)
                 : "memory");
}

// ---------------------------------------------------------------------------
// Kernel 5: finalize  out[n, o] = acc[n, o] * ci[n] + b[o]
// ---------------------------------------------------------------------------
__global__ void finalize_kernel(const float* __restrict__ acc,
                                const float* __restrict__ ci,
                                const float* __restrict__ b,
                                float* __restrict__ out, int n)
{
    int idx = blockIdx.x * blockDim.x + threadIdx.x;
    if (idx >= n * OUTD) return;
    int row = idx >> 7;
    int o = idx & (OUTD - 1);
    out[idx] = acc[idx] * ci[row] + b[o];
}

// ---------------------------------------------------------------------------
// Host launcher
// ---------------------------------------------------------------------------
extern "C" void kernel_launch(void* const* d_in, const int* in_sizes, int n_in,
                              void* d_out, int out_size)
{
    const float* ufeat   = (const float*)d_in[0];
    const float* ifeat   = (const float*)d_in[1];
    const float* cj_user = (const float*)d_in[2];
    const float* ci_user = (const float*)d_in[3];
    const float* cj_item = (const float*)d_in[4];
    const float* ci_item = (const float*)d_in[5];
    const float* W_u     = (const float*)d_in[6];
    const float* W_i     = (const float*)d_in[7];
    const float* Wu_fc   = (const float*)d_in[8];
    const float* bu      = (const float*)d_in[9];
    const float* Wi_fc   = (const float*)d_in[10];
    const float* bi      = (const float*)d_in[11];
    const int*   edge_u  = (const int*)d_in[12];
    const int*   edge_i  = (const int*)d_in[13];
    float* out = (float*)d_out;

    float *xu, *xi, *accu, *acci, *wcu, *wci;
    cudaGetSymbolAddress((void**)&xu,   g_xu);
    cudaGetSymbolAddress((void**)&xi,   g_xi);
    cudaGetSymbolAddress((void**)&accu, g_accu);
    cudaGetSymbolAddress((void**)&acci, g_acci);
    cudaGetSymbolAddress((void**)&wcu,  g_wcu);
    cudaGetSymbolAddress((void**)&wci,  g_wci);

    // 1) Fold per-relation projection into FC slice.
    //    user messages feed ITEM outputs -> Wi_fc; item messages feed USER outputs -> Wu_fc.
    int ctotal = KDIM * NCOMB;
    combine_w_kernel<<<(ctotal + 255) / 256, 256>>>(W_u, Wi_fc, wcu);
    combine_w_kernel<<<(ctotal + 255) / 256, 256>>>(W_i, Wu_fc, wci);

    // 2) Zero accumulators.
    zero_kernel<<<((NU * OUTD / 4) + 255) / 256, 256>>>((float4*)accu, NU * OUTD / 4);
    zero_kernel<<<((NI * OUTD / 4) + 255) / 256, 256>>>((float4*)acci, NI * OUTD / 4);

    // 3) Fused message GEMMs (with cj source scaling folded into the store).
    dim3 gu(NCOMB / 128, (NU + 127) / 128);
    gemm_scale_kernel<<<gu, 256>>>(ufeat, wcu, cj_user, xu, NU);
    dim3 gi(NCOMB / 128, (NI + 127) / 128);
    gemm_scale_kernel<<<gi, 256>>>(ifeat, wci, cj_item, xi, NI);

    // 4) Edge scatter, both directions (all 5 relations accumulate into one 128-wide buffer).
    long long totw = (long long)RREL * NE;
    int sblocks = (int)((totw * 32 + 255) / 256);
    scatter_kernel<<<sblocks, 256>>>(xu, edge_u, edge_i, acci);  // user -> item
    scatter_kernel<<<sblocks, 256>>>(xi, edge_i, edge_u, accu);  // item -> user

    // 5) Finalize: destination ci scaling + bias. Output = [new_u | new_i].
    finalize_kernel<<<((NU * OUTD) + 255) / 256, 256>>>(accu, ci_user, bu, out, NU);
    finalize_kernel<<<((NI * OUTD) + 255) / 256, 256>>>(acci, ci_item, bi,
                                                        out + (size_t)NU * OUTD, NI);
}

// round 9
// speedup vs baseline: 1.0008x; 1.0008x over previous
#include <cuda_runtime.h>
#include <cstdint>
#include <cstddef>

// ---------------------------------------------------------------------------
// Problem constants (fixed shapes per reference)
// ---------------------------------------------------------------------------
#define NU    100000
#define NI    50000
#define KDIM  256
#define MSGD  128
#define OUTD  128
#define RREL  5
#define NE    1000000
#define NCOMB (RREL * OUTD)   // 640

// ---------------------------------------------------------------------------
// Static device scratch (no runtime allocation allowed)
// ---------------------------------------------------------------------------
static __device__ float g_xu[(size_t)NU * NCOMB];     // 256 MB: per-relation user messages (post W-combine)
static __device__ float g_xi[(size_t)NI * NCOMB];     // 128 MB: per-relation item messages
static __device__ float g_accu[(size_t)NU * OUTD];    // 51.2 MB
static __device__ float g_acci[(size_t)NI * OUTD];    // 25.6 MB
static __device__ float g_wcu[KDIM * NCOMB];          // W_u[r] @ Wi_fc_r   (user feats -> item outputs)
static __device__ float g_wci[KDIM * NCOMB];          // W_i[r] @ Wu_fc_r   (item feats -> user outputs)

// ---------------------------------------------------------------------------
// Kernel 1: combine weights  Wc[k][r*128+o] = sum_m W[r,k,m] * Wfc[r*128+m, o]
// ---------------------------------------------------------------------------
__global__ void combine_w_kernel(const float* __restrict__ W,
                                 const float* __restrict__ Wfc,
                                 float* __restrict__ Wc)
{
    int idx = blockIdx.x * blockDim.x + threadIdx.x;
    if (idx >= KDIM * NCOMB) return;
    int k = idx / NCOMB;
    int c = idx - k * NCOMB;
    int r = c / OUTD;
    int o = c - r * OUTD;
    const float* wrow = W + ((size_t)r * KDIM + k) * MSGD;
    const float* fc   = Wfc + ((size_t)r * MSGD) * OUTD + o;
    float s = 0.f;
#pragma unroll 8
    for (int m = 0; m < MSGD; ++m)
        s += wrow[m] * fc[(size_t)m * OUTD];
    Wc[idx] = s;
}

// ---------------------------------------------------------------------------
// Kernel 2: zero accumulators
// ---------------------------------------------------------------------------
__global__ void zero_kernel(float4* __restrict__ p, int n4)
{
    int i = blockIdx.x * blockDim.x + threadIdx.x;
    if (i < n4) p[i] = make_float4(0.f, 0.f, 0.f, 0.f);
}

// ---------------------------------------------------------------------------
// Kernel 3: SGEMM  X[m, :] = (A[m, :256] @ B[256, 640]) * cj[m]
// 128x128 block tile, BK=8, 8x8 per-thread register tile, 256 threads.
// ---------------------------------------------------------------------------
__global__ __launch_bounds__(256, 1) void gemm_scale_kernel(
    const float* __restrict__ A,   // [M, 256]
    const float* __restrict__ B,   // [256, 640]
    const float* __restrict__ cj,  // [M]
    float* __restrict__ X,         // [M, 640]
    int M)
{
    constexpr int K = KDIM;
    constexpr int N = NCOMB;
    __shared__ float As[8][128];
    __shared__ float Bs[8][128];

    const int t = threadIdx.x;
    const int rowBase = blockIdx.y * 128;
    const int colBase = blockIdx.x * 128;

    const int aRow = t >> 1;            // 0..127
    const int aCol = (t & 1) << 2;      // 0 or 4
    const int bRow = t >> 5;            // 0..7
    const int bCol = (t & 31) << 2;     // 0..124

    const int tx = (t & 15) << 3;       // col offset in tile
    const int ty = (t >> 4) << 3;       // row offset in tile

    float acc[8][8];
#pragma unroll
    for (int i = 0; i < 8; ++i)
#pragma unroll
        for (int j = 0; j < 8; ++j) acc[i][j] = 0.f;

    const int grA = rowBase + aRow;
    const bool aValid = (grA < M);

    for (int k0 = 0; k0 < K; k0 += 8) {
        float4 av = make_float4(0.f, 0.f, 0.f, 0.f);
        if (aValid)
            av = *(const float4*)(A + (size_t)grA * K + k0 + aCol);
        As[aCol + 0][aRow] = av.x;
        As[aCol + 1][aRow] = av.y;
        As[aCol + 2][aRow] = av.z;
        As[aCol + 3][aRow] = av.w;

        float4 bv = *(const float4*)(B + (size_t)(k0 + bRow) * N + colBase + bCol);
        *(float4*)&Bs[bRow][bCol] = bv;

        __syncthreads();

#pragma unroll
        for (int k = 0; k < 8; ++k) {
            float a[8], b[8];
            *(float4*)&a[0] = *(const float4*)&As[k][ty];
            *(float4*)&a[4] = *(const float4*)&As[k][ty + 4];
            *(float4*)&b[0] = *(const float4*)&Bs[k][tx];
            *(float4*)&b[4] = *(const float4*)&Bs[k][tx + 4];
#pragma unroll
            for (int i = 0; i < 8; ++i)
#pragma unroll
                for (int j = 0; j < 8; ++j)
                    acc[i][j] += a[i] * b[j];
        }
        __syncthreads();
    }

#pragma unroll
    for (int i = 0; i < 8; ++i) {
        int gr = rowBase + ty + i;
        if (gr < M) {
            float c = cj[gr];
            float4 o0, o1;
            o0.x = acc[i][0] * c; o0.y = acc[i][1] * c;
            o0.z = acc[i][2] * c; o0.w = acc[i][3] * c;
            o1.x = acc[i][4] * c; o1.y = acc[i][5] * c;
            o1.z = acc[i][6] * c; o1.w = acc[i][7] * c;
            *(float4*)(X + (size_t)gr * N + colBase + tx)     = o0;
            *(float4*)(X + (size_t)gr * N + colBase + tx + 4) = o1;
        }
    }
}

// ---------------------------------------------------------------------------
// Kernel 4: edge scatter. One warp per edge: gather 128-float message row,
// vector-reduce-add into destination accumulator row.
// edge arrays are [R, E] flattened, so the flat warp index == r*NE + e.
// ---------------------------------------------------------------------------
__global__ __launch_bounds__(256) void scatter_kernel(
    const float* __restrict__ X,      // [n_src, 640]
    const int* __restrict__ esrc,     // [R*E]
    const int* __restrict__ edst,     // [R*E]
    float* __restrict__ acc)          // [n_dst, 128]
{
    long long w = (long long)blockIdx.x * 8 + (threadIdx.x >> 5);
    if (w >= (long long)RREL * NE) return;
    int lane = threadIdx.x & 31;
    int r = (int)(w / NE);
    int src = esrc[w];
    int dst = edst[w];

    const float4* xp = (const float4*)(X + (size_t)src * NCOMB + (size_t)r * OUTD);
    float4 v = xp[lane];

    float* ap = acc + (size_t)dst * OUTD + lane * 4;
    asm volatile("red.global.add.v4.f32 [%0], {%1, %2, %3, %4};"
                 :: "l"(ap), "f"(v.x), "f"(v.y), "f"(v.z), "f"(v.w)
                 : "memory");
}

// ---------------------------------------------------------------------------
// Kernel 5: finalize  out[n, o] = acc[n, o] * ci[n] + b[o]
// ---------------------------------------------------------------------------
__global__ void finalize_kernel(const float* __restrict__ acc,
                                const float* __restrict__ ci,
                                const float* __restrict__ b,
                                float* __restrict__ out, int n)
{
    int idx = blockIdx.x * blockDim.x + threadIdx.x;
    if (idx >= n * OUTD) return;
    int row = idx >> 7;
    int o = idx & (OUTD - 1);
    out[idx] = acc[idx] * ci[row] + b[o];
}

// ---------------------------------------------------------------------------
// Host launcher
// ---------------------------------------------------------------------------
extern "C" void kernel_launch(void* const* d_in, const int* in_sizes, int n_in,
                              void* d_out, int out_size)
{
    const float* ufeat   = (const float*)d_in[0];
    const float* ifeat   = (const float*)d_in[1];
    const float* cj_user = (const float*)d_in[2];
    const float* ci_user = (const float*)d_in[3];
    const float* cj_item = (const float*)d_in[4];
    const float* ci_item = (const float*)d_in[5];
    const float* W_u     = (const float*)d_in[6];
    const float* W_i     = (const float*)d_in[7];
    const float* Wu_fc   = (const float*)d_in[8];
    const float* bu      = (const float*)d_in[9];
    const float* Wi_fc   = (const float*)d_in[10];
    const float* bi      = (const float*)d_in[11];
    const int*   edge_u  = (const int*)d_in[12];
    const int*   edge_i  = (const int*)d_in[13];
    float* out = (float*)d_out;

    float *xu, *xi, *accu, *acci, *wcu, *wci;
    cudaGetSymbolAddress((void**)&xu,   g_xu);
    cudaGetSymbolAddress((void**)&xi,   g_xi);
    cudaGetSymbolAddress((void**)&accu, g_accu);
    cudaGetSymbolAddress((void**)&acci, g_acci);
    cudaGetSymbolAddress((void**)&wcu,  g_wcu);
    cudaGetSymbolAddress((void**)&wci,  g_wci);

    // 1) Fold per-relation projection into FC slice.
    //    user messages feed ITEM outputs -> Wi_fc; item messages feed USER outputs -> Wu_fc.
    int ctotal = KDIM * NCOMB;
    combine_w_kernel<<<(ctotal + 255) / 256, 256>>>(W_u, Wi_fc, wcu);
    combine_w_kernel<<<(ctotal + 255) / 256, 256>>>(W_i, Wu_fc, wci);

    // 2) Zero accumulators.
    zero_kernel<<<((NU * OUTD / 4) + 255) / 256, 256>>>((float4*)accu, NU * OUTD / 4);
    zero_kernel<<<((NI * OUTD / 4) + 255) / 256, 256>>>((float4*)acci, NI * OUTD / 4);

    // 3) Fused message GEMMs (with cj source scaling folded into the store).
    dim3 gu(NCOMB / 128, (NU + 127) / 128);
    gemm_scale_kernel<<<gu, 256>>>(ufeat, wcu, cj_user, xu, NU);
    dim3 gi(NCOMB / 128, (NI + 127) / 128);
    gemm_scale_kernel<<<gi, 256>>>(ifeat, wci, cj_item, xi, NI);

    // 4) Edge scatter, both directions (all 5 relations accumulate into one 128-wide buffer).
    long long totw = (long long)RREL * NE;
    int sblocks = (int)((totw * 32 + 255) / 256);
    scatter_kernel<<<sblocks, 256>>>(xu, edge_u, edge_i, acci);  // user -> item
    scatter_kernel<<<sblocks, 256>>>(xi, edge_i, edge_u, accu);  // item -> user

    // 5) Finalize: destination ci scaling + bias. Output = [new_u | new_i].
    finalize_kernel<<<((NU * OUTD) + 255) / 256, 256>>>(accu, ci_user, bu, out, NU);
    finalize_kernel<<<((NI * OUTD) + 255) / 256, 256>>>(acci, ci_item, bi,
                                                        out + (size_t)NU * OUTD, NI);
}